// round 8
// baseline (speedup 1.0000x reference)
#include <cuda_runtime.h>
#include <cuda_fp16.h>
#include <cstdint>

#define B_    16
#define T_    4096
#define DIM_  256
#define H_    128
#define G3    384
#define BT    65536   // B_*T_
#define CHUNK 128
#define NCHUNK 32     // T_/CHUNK
#define NMT   512     // BT/128 m-tiles
#define NNT   4       // 384/96 n-tiles
#define TICKETS (2*NMT*NNT)  // 4096 per layer
#define SPIN_CAP (1u << 21)  // bounded spins: deadlock -> wrong answer, not hang

// Scratch: two xg buffers (layer parity), two activation buffers, sync state.
__device__ float g_xg[2][2ull * BT * G3];       // 2 x 201 MB
__device__ float g_buf[2][(size_t)BT * DIM_];   // 2 x 64 MB
__device__ int g_tileflag[3][2][NMT];           // n-tiles done per (l,d,mtile)
__device__ int g_prog[3][2][B_];                // rnn steps done per (l,d,b)
__device__ int g_ticket[3];                     // gemm work queue heads

typedef unsigned long long ull;

// Compiler-opaque CTA barrier: cannot be merged/eliminated/moved by NVVM.
// All 12 warps arrive (possibly at different PCs); HW counts arrivals on
// barrier 0, so matched per-iteration counts across roles are guaranteed.
__device__ __forceinline__ void barrier_cta() {
    asm volatile("bar.sync 0;" ::: "memory");
}

__device__ __forceinline__ ull ffma2(ull a, ull b, ull c) {
    ull d;
    asm("fma.rn.f32x2 %0, %1, %2, %3;" : "=l"(d) : "l"(a), "l"(b), "l"(c));
    return d;
}
__device__ __forceinline__ ull fpack2(float lo, float hi) {
    ull r;
    asm("mov.b64 %0, {%1, %2};" : "=l"(r) : "f"(lo), "f"(hi));
    return r;
}
__device__ __forceinline__ float2 funpack(ull v) {
    float2 r;
    asm("mov.b64 {%0, %1}, %2;" : "=f"(r.x), "=f"(r.y) : "l"(v));
    return r;
}
__device__ __forceinline__ float sigmoidf_fast(float x) {
    return __fdividef(1.0f, 1.0f + __expf(-x));
}
__device__ __forceinline__ float tanhf_fast(float x) {
    return __fdividef(2.0f, 1.0f + __expf(-2.0f * x)) - 1.0f;
}
__device__ __forceinline__ void spin_ge(volatile int* p, int need, int ns) {
    unsigned it = 0;
    while (*p < need && ++it < SPIN_CAP) __nanosleep(ns);
}

__global__ void init_sync() {
    int i = blockIdx.x * blockDim.x + threadIdx.x;
    if (i < 3 * 2 * NMT) ((int*)g_tileflag)[i] = 0;
    if (i < 3 * 2 * B_) ((int*)g_prog)[i] = 0;
    if (i < 3) g_ticket[i] = 0;
}

// ---------------------------------------------------------------------------
// Fused persistent kernel. Blocks 0..31: recurrence chains (b,d) through all
// 3 layers. Blocks 32..147: gemm workers producing xg tiles from a ticket
// queue, gated on recurrence progress. All 148 CTAs co-resident (occ 1).
//
// Recurrence warp roles (asm barriers; arrival counts match by construction):
//   threads 0..255 (gates r,z): fp16 HFMA2 dot (rate-2) on fp16 Wh + fp16 h.
//   threads 256..383 (gate n):  fp32 FFMA2 dot (n feeds h directly).
// ---------------------------------------------------------------------------
__global__ void __launch_bounds__(384, 1) mega(const float* __restrict__ xin,
                                               const float* __restrict__ Wi,
                                               const float* __restrict__ Wh,
                                               const float* __restrict__ bh,
                                               float* __restrict__ out) {
    const int tid = threadIdx.x;

    if (blockIdx.x < 32) {
        // =================== recurrence CTA: chain (b,d) ===================
        const int b = blockIdx.x & 15;
        const int d = blockIdx.x >> 4;
        const int c0 = tid & 127;
        const int gate = tid >> 7;  // 0=r, 1=z, 2=n

        __shared__ __align__(16) float h_s[H_];     // fp32 h (n path)
        __shared__ __align__(16) __half hh16[H_];   // fp16 h (r/z path)
        __shared__ float rr[H_];
        __shared__ float zz[H_];

        const int sd = d ? -1 : 1;
        const long xstep = (long)sd * G3;
        const long ystep = (long)sd * DIM_;

        if (gate < 2) {
            // ======================= r/z role (fp16 dot) ===================
            for (int l = 0; l < 3; l++) {
                const float* __restrict__ W = Wh + (size_t)(l * 2 + d) * H_ * G3;
                const float* __restrict__ xgb =
                    g_xg[l & 1] + ((size_t)d * BT + (size_t)b * T_) * G3;

                __half2 w16[64];
                {
                    const float* Wc = W + tid;
#pragma unroll
                    for (int m = 0; m < 64; m++)
                        w16[m] = __floats2half2_rn(Wc[(size_t)(2 * m) * G3],
                                                   Wc[(size_t)(2 * m + 1) * G3]);
                }
                const float bias = bh[(size_t)(l * 2 + d) * G3 + tid];

                if (tid < H_) {
                    h_s[tid] = 0.0f;
                    hh16[tid] = __float2half(0.0f);
                }

                const float* xp = xgb + (d ? (size_t)(T_ - 1) * G3 : 0) + tid;

                if (tid == 0) {
                    int tc0 = d ? (NCHUNK - 1) : 0;
                    spin_ge(&g_tileflag[l][d][b * NCHUNK + tc0], NNT, 128);
                    __threadfence();
                }
                barrier_cta();  // [A]
                float xv = *xp + bias;
                xp += xstep;

                const uint4* const hh4 = (const uint4*)hh16;

                for (int c = 0; c < NCHUNK; c++) {
                    if (tid == 0 && c + 1 < NCHUNK) {
                        int tcn = d ? (NCHUNK - 2 - c) : (c + 1);
                        spin_ge(&g_tileflag[l][d][b * NCHUNK + tcn], NNT, 128);
                        __threadfence();
                    }
                    barrier_cta();  // [B]

#pragma unroll 1
                    for (int t2 = 0; t2 < CHUNK; t2++) {
                        // fp16 dot: 16 broadcast LDS.128, 64 HFMA2, 8 accs
                        // (max 8 sequential fp16 adds per accumulator).
                        __half2 hacc[8];
#pragma unroll
                        for (int i = 0; i < 8; i++)
                            hacc[i] = __floats2half2_rn(0.0f, 0.0f);
#pragma unroll
                        for (int j = 0; j < 16; j++) {
                            uint4 v = hh4[j];
                            __half2 h0 = *reinterpret_cast<const __half2*>(&v.x);
                            __half2 h1 = *reinterpret_cast<const __half2*>(&v.y);
                            __half2 h2 = *reinterpret_cast<const __half2*>(&v.z);
                            __half2 h3 = *reinterpret_cast<const __half2*>(&v.w);
                            int a0 = (4 * j) & 7;
                            hacc[a0 + 0] = __hfma2(w16[4 * j + 0], h0, hacc[a0 + 0]);
                            hacc[a0 + 1] = __hfma2(w16[4 * j + 1], h1, hacc[a0 + 1]);
                            hacc[a0 + 2] = __hfma2(w16[4 * j + 2], h2, hacc[a0 + 2]);
                            hacc[a0 + 3] = __hfma2(w16[4 * j + 3], h3, hacc[a0 + 3]);
                        }
                        float2 f0 = __half22float2(hacc[0]);
                        float2 f1 = __half22float2(hacc[1]);
                        float2 f2 = __half22float2(hacc[2]);
                        float2 f3 = __half22float2(hacc[3]);
                        float2 f4 = __half22float2(hacc[4]);
                        float2 f5 = __half22float2(hacc[5]);
                        float2 f6 = __half22float2(hacc[6]);
                        float2 f7 = __half22float2(hacc[7]);
                        float s01 = (f0.x + f0.y) + (f1.x + f1.y);
                        float s23 = (f2.x + f2.y) + (f3.x + f3.y);
                        float s45 = (f4.x + f4.y) + (f5.x + f5.y);
                        float s67 = (f6.x + f6.y) + (f7.x + f7.y);
                        float dot = (s01 + s23) + (s45 + s67);

                        // Prefetch next step's xg (one-past-end stays in g_xg).
                        float nxv = *xp + bias;
                        xp += xstep;

                        if (gate == 0) {
                            rr[c0] = sigmoidf_fast(xv + dot);
                        } else {
                            zz[c0] = sigmoidf_fast(xv + dot);
                        }
                        barrier_cta();  // bar1: r,z published
                        barrier_cta();  // bar2: new h visible
                        xv = nxv;
                    }

                    __threadfence();
                    barrier_cta();  // [C]
                    if (tid == 0) atomicExch(&g_prog[l][d][b], (c + 1) * CHUNK);
                }
                barrier_cta();  // [D]
            }
        } else {
            // ========================= n role (fp32 dot) ===================
            for (int l = 0; l < 3; l++) {
                float* __restrict__ Y = (l == 2) ? out : g_buf[l];
                const float* __restrict__ W = Wh + (size_t)(l * 2 + d) * H_ * G3;
                const float* __restrict__ xgb =
                    g_xg[l & 1] + ((size_t)d * BT + (size_t)b * T_) * G3;

                ull w[64];
                {
                    const float* Wc = W + 256 + c0;  // column 256+c0
#pragma unroll
                    for (int j = 0; j < 64; j++)
                        w[j] = fpack2(Wc[(size_t)(2 * j) * G3],
                                      Wc[(size_t)(2 * j + 1) * G3]);
                }
                const float bias = bh[(size_t)(l * 2 + d) * G3 + 256 + c0];

                const float* xp = xgb + (d ? (size_t)(T_ - 1) * G3 : 0) + 256 + c0;
                float* yp = Y + (size_t)b * T_ * DIM_ + d * H_ + c0 +
                            (d ? (size_t)(T_ - 1) * DIM_ : 0);

                barrier_cta();  // [A]
                float xv = *xp;
                xp += xstep;

                const ulonglong2* const hp = (const ulonglong2*)h_s;

                for (int c = 0; c < NCHUNK; c++) {
                    barrier_cta();  // [B]

#pragma unroll 1
                    for (int t2 = 0; t2 < CHUNK; t2++) {
                        // fp32 dot: 32 broadcast LDS.128, 64 FFMA2.
                        ull acc0 = 0, acc1 = 0;
#pragma unroll
                        for (int j = 0; j < 32; j++) {
                            ulonglong2 hv = hp[j];
                            acc0 = ffma2(w[2 * j], hv.x, acc0);
                            acc1 = ffma2(w[2 * j + 1], hv.y, acc1);
                        }
                        float2 lo = funpack(acc0), hi = funpack(acc1);
                        float dot = (lo.x + lo.y) + (hi.x + hi.y);

                        float nxv = *xp;
                        xp += xstep;

                        float dn = dot + bias;
                        barrier_cta();  // bar1: r,z published

                        float r = rr[c0];
                        float z = zz[c0];
                        float hold = h_s[c0];
                        float n = tanhf_fast(fmaf(r, dn, xv));
                        float hnew = fmaf(z, hold - n, n);
                        h_s[c0] = hnew;
                        hh16[c0] = __float2half(hnew);
                        *yp = hnew;
                        barrier_cta();  // bar2: new h visible

                        xv = nxv;
                        yp += ystep;
                    }

                    __threadfence();
                    barrier_cta();  // [C]
                }
                barrier_cta();  // [D]
            }
        }
    } else {
        // ======================= gemm worker CTA ==========================
        // xg[l][d][bt][c] = sum_k X[bt][k] * Wi[l][d][k][c]
        // BM=128, BN=96, BK=16, 384 threads, 8x4 micro-tile.
        __shared__ __align__(16) float As[16][128];
        __shared__ __align__(16) float Bs[16][96];
        __shared__ int sh_tk;

        const int ar = tid >> 1;             // A fill row (tid<256)
        const int akq = (tid & 1) * 8;       // A fill k-octet
        const int bk = tid / 24;             // B fill k-row 0..15
        const int bc = (tid % 24) * 4;       // B fill col
        const int ry = (tid / 24) * 8;       // micro rows
        const int cx = (tid % 24) * 4;       // micro cols

        for (int l = 0; l < 3; l++) {
            const float* __restrict__ X = (l == 0) ? xin : g_buf[l - 1];
            float* __restrict__ Cb = g_xg[l & 1];

            while (true) {
                if (tid == 0) sh_tk = atomicAdd(&g_ticket[l], 1);
                __syncthreads();
                int tk = sh_tk;
                if (tk >= TICKETS) break;

                // Decode ticket -> (tc, d, b, nt). Layer 0: ends-first tc
                // order (matches rnn consumption); layers 1-2: middle-out
                // (matches readiness).
                int i = tk >> 7;       // 0..31
                int rem = tk & 127;
                int tc;
                if (l == 0) {
                    tc = (i & 1) ? (31 - (i >> 1)) : (i >> 1);
                } else {
                    tc = (i & 1) ? (16 + (i >> 1)) : (15 - (i >> 1));
                }
                int d = rem >> 6;
                int b = (rem >> 2) & 15;
                int nt = rem & 3;
                int m = b * NCHUNK + tc;

                // Gate on upstream recurrence progress (acquire).
                if (l > 0) {
                    if (tid == 0) {
                        spin_ge(&g_prog[l - 1][0][b], (tc + 1) * CHUNK, 256);
                        spin_ge(&g_prog[l - 1][1][b], T_ - tc * CHUNK, 256);
                        __threadfence();
                    }
                    __syncthreads();
                }

                const int m0 = m * 128;
                const int n0 = nt * 96;
                const float* __restrict__ W =
                    Wi + (size_t)(l * 2 + d) * DIM_ * G3;
                float* __restrict__ C = Cb + (size_t)d * BT * G3;

                const float* Ap = X + (size_t)(m0 + ar) * DIM_ + akq;
                const float* Bp = W + (size_t)bk * G3 + n0 + bc;

                float acc[8][4];
#pragma unroll
                for (int ii = 0; ii < 8; ii++)
#pragma unroll
                    for (int jj = 0; jj < 4; jj++) acc[ii][jj] = 0.0f;

                float4 a0, a1, b0;
                if (tid < 256) {
                    a0 = *(const float4*)(Ap);
                    a1 = *(const float4*)(Ap + 4);
                }
                b0 = *(const float4*)(Bp);

#pragma unroll 1
                for (int k0 = 0; k0 < DIM_; k0 += 16) {
                    if (tid < 256) {
                        As[akq + 0][ar] = a0.x; As[akq + 1][ar] = a0.y;
                        As[akq + 2][ar] = a0.z; As[akq + 3][ar] = a0.w;
                        As[akq + 4][ar] = a1.x; As[akq + 5][ar] = a1.y;
                        As[akq + 6][ar] = a1.z; As[akq + 7][ar] = a1.w;
                    }
                    *(float4*)&Bs[bk][bc] = b0;
                    __syncthreads();

                    if (k0 + 16 < DIM_) {
                        if (tid < 256) {
                            a0 = *(const float4*)(Ap + k0 + 16);
                            a1 = *(const float4*)(Ap + k0 + 20);
                        }
                        b0 = *(const float4*)(Bp + (size_t)(k0 + 16) * G3);
                    }

#pragma unroll
                    for (int k = 0; k < 16; k++) {
                        float4 av0 = *(const float4*)&As[k][ry];
                        float4 av1 = *(const float4*)&As[k][ry + 4];
                        float4 bv = *(const float4*)&Bs[k][cx];
                        float a[8] = {av0.x, av0.y, av0.z, av0.w,
                                      av1.x, av1.y, av1.z, av1.w};
                        float bb2[4] = {bv.x, bv.y, bv.z, bv.w};
#pragma unroll
                        for (int ii = 0; ii < 8; ii++)
#pragma unroll
                            for (int jj = 0; jj < 4; jj++)
                                acc[ii][jj] = fmaf(a[ii], bb2[jj], acc[ii][jj]);
                    }
                    __syncthreads();
                }

#pragma unroll
                for (int ii = 0; ii < 8; ii++) {
                    float* crow = C + (size_t)(m0 + ry + ii) * G3 + n0 + cx;
                    *(float4*)crow =
                        make_float4(acc[ii][0], acc[ii][1], acc[ii][2], acc[ii][3]);
                }

                // Publish tile (release).
                __threadfence();
                __syncthreads();
                if (tid == 0) atomicAdd(&g_tileflag[l][d][m], 1);
            }
        }
    }
}

// ---------------------------------------------------------------------------
extern "C" void kernel_launch(void* const* d_in, const int* in_sizes, int n_in,
                              void* d_out, int out_size) {
    (void)in_sizes;
    (void)n_in;
    (void)out_size;
    const float* x = (const float*)d_in[0];    // [16,4096,256]
    const float* Wi = (const float*)d_in[1];   // [3,2,256,384]
    const float* Wh = (const float*)d_in[2];   // [3,2,128,384]
    const float* bh = (const float*)d_in[3];   // [3,2,384]
    float* out = (float*)d_out;                // [16,4096,256]

    init_sync<<<13, 256>>>();
    mega<<<148, 384>>>(x, Wi, Wh, bh, out);
}

// round 9
// speedup vs baseline: 1.0080x; 1.0080x over previous
#include <cuda_runtime.h>
#include <cstdint>

#define B_    16
#define T_    4096
#define DIM_  256
#define H_    128
#define G3    384
#define BT    65536   // B_*T_
#define CHUNK 128
#define NCHUNK 32     // T_/CHUNK
#define NMT   512     // BT/128 m-tiles
#define NNT   4       // 384/96 n-tiles
#define TICKETS (2*NMT*NNT)  // 4096 per layer
#define SPIN_CAP (1u << 21)
#define WAIT_CAP (1u << 16)

// Scratch: two xg buffers (layer parity), two activation buffers, sync state.
__device__ float g_xg[2][2ull * BT * G3];       // 2 x 201 MB
__device__ float g_buf[2][(size_t)BT * DIM_];   // 2 x 64 MB
__device__ int g_tileflag[3][2][NMT];           // n-tiles done per (l,d,mtile)
__device__ int g_prog[3][2][B_];                // rnn steps done per (l,d,b)
__device__ int g_ticket[3];                     // gemm work queue heads

typedef unsigned long long ull;

__device__ __forceinline__ ull ffma2(ull a, ull b, ull c) {
    ull d;
    asm("fma.rn.f32x2 %0, %1, %2, %3;" : "=l"(d) : "l"(a), "l"(b), "l"(c));
    return d;
}
__device__ __forceinline__ ull fpack2(float lo, float hi) {
    ull r;
    asm("mov.b64 %0, {%1, %2};" : "=l"(r) : "f"(lo), "f"(hi));
    return r;
}
__device__ __forceinline__ float2 funpack(ull v) {
    float2 r;
    asm("mov.b64 {%0, %1}, %2;" : "=f"(r.x), "=f"(r.y) : "l"(v));
    return r;
}
__device__ __forceinline__ float sigmoidf_fast(float x) {
    return __fdividef(1.0f, 1.0f + __expf(-x));
}
__device__ __forceinline__ float tanhf_fast(float x) {
    return __fdividef(2.0f, 1.0f + __expf(-2.0f * x)) - 1.0f;
}
__device__ __forceinline__ void spin_ge(volatile int* p, int need, int ns) {
    unsigned it = 0;
    while (*p < need && ++it < SPIN_CAP) __nanosleep(ns);
}
__device__ __forceinline__ uint32_t smem_u32(const void* p) {
    uint32_t a;
    asm("{ .reg .u64 t; cvta.to.shared.u64 t, %1; cvt.u32.u64 %0, t; }"
        : "=r"(a) : "l"(p));
    return a;
}
__device__ __forceinline__ uint32_t mapa_u32(uint32_t local, uint32_t rank) {
    uint32_t r;
    asm("mapa.shared::cluster.u32 %0, %1, %2;" : "=r"(r) : "r"(local), "r"(rank));
    return r;
}
// Remote push of one b32 + mbarrier transaction accounting (one crossbar trip).
__device__ __forceinline__ void st_async_b32(uint32_t raddr, float v, uint32_t rmbar) {
    asm volatile(
        "st.async.shared::cluster.mbarrier::complete_tx::bytes.b32 [%0], %1, [%2];"
        :: "r"(raddr), "r"(__float_as_uint(v)), "r"(rmbar) : "memory");
}
__device__ __forceinline__ void mbar_expect_tx(uint32_t mbar, uint32_t bytes) {
    asm volatile("mbarrier.arrive.expect_tx.shared.b64 _, [%0], %1;"
                 :: "r"(mbar), "r"(bytes) : "memory");
}
__device__ __forceinline__ void mbar_wait(uint32_t mbar, uint32_t ph) {
    uint32_t done;
    unsigned it = 0;
    do {
        asm volatile(
            "{\n\t.reg .pred p;\n\t"
            "mbarrier.try_wait.parity.acquire.cta.shared::cta.b64 p, [%1], %2, 0x989680;\n\t"
            "selp.b32 %0, 1, 0, p;\n\t}"
            : "=r"(done) : "r"(mbar), "r"(ph) : "memory");
    } while (!done && ++it < WAIT_CAP);
}

__global__ void init_sync() {
    int i = blockIdx.x * blockDim.x + threadIdx.x;
    if (i < 3 * 2 * NMT) ((int*)g_tileflag)[i] = 0;
    if (i < 3 * 2 * B_) ((int*)g_prog)[i] = 0;
    if (i < 3) g_ticket[i] = 0;
}

// ---------------------------------------------------------------------------
// Fused persistent kernel, cluster size 2.
// Blocks 0..63: recurrence. Cluster i = blocks {2i, 2i+1} runs chain
// (b = i&15, d = i>>4). Each CTA's thread t owns a HALF column of Wh
// (rank r covers k in [64r, 64r+64)): per-SM dot issue floor is halved.
// Partials are pushed to the peer via st.async (+mbarrier tx); both CTAs
// then redundantly compute the full gate epilogue (p_local + p_peer is
// commutative -> bit-identical h in both CTAs; no h broadcast needed).
// Blocks 64..147: gemm workers producing xg tiles from a ticket queue.
// ---------------------------------------------------------------------------
__global__ void __launch_bounds__(384, 1) __cluster_dims__(2, 1, 1)
mega(const float* __restrict__ xin,
     const float* __restrict__ Wi,
     const float* __restrict__ Wh,
     const float* __restrict__ bh,
     float* __restrict__ out) {
    const int tid = threadIdx.x;

    if (blockIdx.x < 64) {
        // =================== recurrence cluster CTA ========================
        const int chain = blockIdx.x >> 1;
        const uint32_t rank = blockIdx.x & 1;   // == cluster_ctarank
        const uint32_t peer = rank ^ 1;
        const int b = chain & 15;
        const int d = chain >> 4;
        const int c0 = tid & 127;
        const int gate = tid >> 7;  // 0=r, 1=z, 2=n

        __shared__ __align__(16) float h_s[H_];
        __shared__ float rr[H_];
        __shared__ float zz[H_];
        __shared__ __align__(16) float part[2][G3];   // peer partials, 2-deep
        __shared__ __align__(8) ull mbar[1];

        const uint32_t mbar_l = smem_u32(mbar);
        const uint32_t part_l = smem_u32(part);
        const uint32_t mbar_r = mapa_u32(mbar_l, peer);
        const uint32_t part_r = mapa_u32(part_l, peer) + (uint32_t)tid * 4u;

        if (tid == 0) {
            asm volatile("mbarrier.init.shared.b64 [%0], %1;"
                         :: "r"(mbar_l), "r"(1) : "memory");
        }
        __syncthreads();
        // Peer must see my mbarrier initialized before its first st.async.
        asm volatile("barrier.cluster.arrive.aligned;" ::: "memory");
        asm volatile("barrier.cluster.wait.aligned;" ::: "memory");

        uint32_t ph = 0;   // mbarrier phase parity, flips every step
        uint32_t buf = 0;  // partial double-buffer parity

        const int sd = d ? -1 : 1;
        const long xstep = (long)sd * G3;
        const long ystep = (long)sd * DIM_;

        for (int l = 0; l < 3; l++) {
            float* __restrict__ Y = (l == 2) ? out : g_buf[l];
            const float* __restrict__ W = Wh + (size_t)(l * 2 + d) * H_ * G3;
            const float* __restrict__ xgb =
                g_xg[l & 1] + ((size_t)d * BT + (size_t)b * T_) * G3;

            // Half column: rank r owns k in [64r, 64r+64) of column tid.
            ull w[32];
            {
                const float* Wc = W + (size_t)(64 * rank) * G3 + tid;
#pragma unroll
                for (int j = 0; j < 32; j++)
                    w[j] = fpack2(Wc[(size_t)(2 * j) * G3],
                                  Wc[(size_t)(2 * j + 1) * G3]);
            }
            const float bias = bh[(size_t)(l * 2 + d) * G3 + tid];
            const float badd = (gate == 2) ? 0.0f : bias;

            if (tid < H_) h_s[tid] = 0.0f;

            const float* xp = xgb + (d ? (size_t)(T_ - 1) * G3 : 0) + tid;
            float* yp = Y + (size_t)b * T_ * DIM_ + d * H_ + c0 +
                        (d ? (size_t)(T_ - 1) * DIM_ : 0);

            if (tid == 0) {
                int tc0 = d ? (NCHUNK - 1) : 0;
                spin_ge(&g_tileflag[l][d][b * NCHUNK + tc0], NNT, 128);
                __threadfence();
            }
            __syncthreads();
            float xv = *xp + badd;
            xp += xstep;

            const ulonglong2* const hp =
                (const ulonglong2*)(h_s + 64 * rank);

            for (int c = 0; c < NCHUNK; c++) {
                if (tid == 0 && c + 1 < NCHUNK) {
                    int tcn = d ? (NCHUNK - 2 - c) : (c + 1);
                    spin_ge(&g_tileflag[l][d][b * NCHUNK + tcn], NNT, 128);
                    __threadfence();
                }
                __syncthreads();

#pragma unroll 1
                for (int t2 = 0; t2 < CHUNK; t2++) {
                    // Post this phase's expected bytes (384 x 4B from peer).
                    if (tid == 0) mbar_expect_tx(mbar_l, G3 * 4);

                    // Half dot: 8 broadcast LDS.128, 32 FFMA2.
                    ull acc0 = 0, acc1 = 0;
#pragma unroll
                    for (int j = 0; j < 16; j++) {
                        ulonglong2 hv = hp[j];
                        acc0 = ffma2(w[2 * j], hv.x, acc0);
                        acc1 = ffma2(w[2 * j + 1], hv.y, acc1);
                    }
                    float2 lo = funpack(acc0), hi = funpack(acc1);
                    float p = (lo.x + lo.y) + (hi.x + hi.y);

                    // Push my partial into the peer's buffer for this step.
                    st_async_b32(part_r + buf * (G3 * 4), p, mbar_r);

                    // Prefetch next step's xg (one-past-end stays in g_xg).
                    float nxv = *xp + badd;
                    xp += xstep;

                    // Wait for the peer's 384 partials (phase parity).
                    mbar_wait(mbar_l, ph);
                    float full = p + part[buf][tid];  // commutative: both
                                                      // CTAs get identical h

                    float dn = 0.0f;
                    if (gate == 0) {
                        rr[c0] = sigmoidf_fast(xv + full);
                    } else if (gate == 1) {
                        zz[c0] = sigmoidf_fast(xv + full);
                    } else {
                        dn = full + bias;
                    }
                    __syncthreads();  // bar1: r,z published

                    if (gate == 2) {
                        float r = rr[c0];
                        float z = zz[c0];
                        float hold = h_s[c0];
                        float n = tanhf_fast(fmaf(r, dn, xv));
                        float hnew = fmaf(z, hold - n, n);
                        h_s[c0] = hnew;
                        if (rank == 0) *yp = hnew;
                    }
                    __syncthreads();  // bar2: new h visible locally

                    xv = nxv;
                    yp += ystep;
                    ph ^= 1;
                    buf ^= 1;
                }

                // Publish progress (rank0 only; release: fence -> bar -> flag).
                __threadfence();
                __syncthreads();
                if (tid == 0 && rank == 0)
                    atomicExch(&g_prog[l][d][b], (c + 1) * CHUNK);
            }
            __syncthreads();
        }

        // No CTA may exit while its peer could still st.async into it.
        asm volatile("barrier.cluster.arrive.aligned;" ::: "memory");
        asm volatile("barrier.cluster.wait.aligned;" ::: "memory");
    } else {
        // ======================= gemm worker CTA ==========================
        // xg[l][d][bt][c] = sum_k X[bt][k] * Wi[l][d][k][c]
        // BM=128, BN=96, BK=16, 384 threads, 8x4 micro-tile.
        __shared__ __align__(16) float As[16][128];
        __shared__ __align__(16) float Bs[16][96];
        __shared__ int sh_tk;

        const int ar = tid >> 1;             // A fill row (tid<256)
        const int akq = (tid & 1) * 8;       // A fill k-octet
        const int bk = tid / 24;             // B fill k-row 0..15
        const int bc = (tid % 24) * 4;       // B fill col
        const int ry = (tid / 24) * 8;       // micro rows
        const int cx = (tid % 24) * 4;       // micro cols

        for (int l = 0; l < 3; l++) {
            const float* __restrict__ X = (l == 0) ? xin : g_buf[l - 1];
            float* __restrict__ Cb = g_xg[l & 1];

            while (true) {
                if (tid == 0) sh_tk = atomicAdd(&g_ticket[l], 1);
                __syncthreads();
                int tk = sh_tk;
                if (tk >= TICKETS) break;

                // Decode ticket -> (tc, d, b, nt). Layer 0: ends-first tc
                // order (matches rnn consumption); layers 1-2: middle-out
                // (matches readiness).
                int i = tk >> 7;       // 0..31
                int rem = tk & 127;
                int tc;
                if (l == 0) {
                    tc = (i & 1) ? (31 - (i >> 1)) : (i >> 1);
                } else {
                    tc = (i & 1) ? (16 + (i >> 1)) : (15 - (i >> 1));
                }
                int d = rem >> 6;
                int b = (rem >> 2) & 15;
                int nt = rem & 3;
                int m = b * NCHUNK + tc;

                // Gate on upstream recurrence progress (acquire).
                if (l > 0) {
                    if (tid == 0) {
                        spin_ge(&g_prog[l - 1][0][b], (tc + 1) * CHUNK, 256);
                        spin_ge(&g_prog[l - 1][1][b], T_ - tc * CHUNK, 256);
                        __threadfence();
                    }
                    __syncthreads();
                }

                const int m0 = m * 128;
                const int n0 = nt * 96;
                const float* __restrict__ W =
                    Wi + (size_t)(l * 2 + d) * DIM_ * G3;
                float* __restrict__ C = Cb + (size_t)d * BT * G3;

                const float* Ap = X + (size_t)(m0 + ar) * DIM_ + akq;
                const float* Bp = W + (size_t)bk * G3 + n0 + bc;

                float acc[8][4];
#pragma unroll
                for (int ii = 0; ii < 8; ii++)
#pragma unroll
                    for (int jj = 0; jj < 4; jj++) acc[ii][jj] = 0.0f;

                float4 a0, a1, b0;
                if (tid < 256) {
                    a0 = *(const float4*)(Ap);
                    a1 = *(const float4*)(Ap + 4);
                }
                b0 = *(const float4*)(Bp);

#pragma unroll 1
                for (int k0 = 0; k0 < DIM_; k0 += 16) {
                    if (tid < 256) {
                        As[akq + 0][ar] = a0.x; As[akq + 1][ar] = a0.y;
                        As[akq + 2][ar] = a0.z; As[akq + 3][ar] = a0.w;
                        As[akq + 4][ar] = a1.x; As[akq + 5][ar] = a1.y;
                        As[akq + 6][ar] = a1.z; As[akq + 7][ar] = a1.w;
                    }
                    *(float4*)&Bs[bk][bc] = b0;
                    __syncthreads();

                    if (k0 + 16 < DIM_) {
                        if (tid < 256) {
                            a0 = *(const float4*)(Ap + k0 + 16);
                            a1 = *(const float4*)(Ap + k0 + 20);
                        }
                        b0 = *(const float4*)(Bp + (size_t)(k0 + 16) * G3);
                    }

#pragma unroll
                    for (int k = 0; k < 16; k++) {
                        float4 av0 = *(const float4*)&As[k][ry];
                        float4 av1 = *(const float4*)&As[k][ry + 4];
                        float4 bv = *(const float4*)&Bs[k][cx];
                        float a[8] = {av0.x, av0.y, av0.z, av0.w,
                                      av1.x, av1.y, av1.z, av1.w};
                        float bb2[4] = {bv.x, bv.y, bv.z, bv.w};
#pragma unroll
                        for (int ii = 0; ii < 8; ii++)
#pragma unroll
                            for (int jj = 0; jj < 4; jj++)
                                acc[ii][jj] = fmaf(a[ii], bb2[jj], acc[ii][jj]);
                    }
                    __syncthreads();
                }

#pragma unroll
                for (int ii = 0; ii < 8; ii++) {
                    float* crow = C + (size_t)(m0 + ry + ii) * G3 + n0 + cx;
                    *(float4*)crow =
                        make_float4(acc[ii][0], acc[ii][1], acc[ii][2], acc[ii][3]);
                }

                // Publish tile (release).
                __threadfence();
                __syncthreads();
                if (tid == 0) atomicAdd(&g_tileflag[l][d][m], 1);
            }
        }
    }
}

// ---------------------------------------------------------------------------
extern "C" void kernel_launch(void* const* d_in, const int* in_sizes, int n_in,
                              void* d_out, int out_size) {
    (void)in_sizes;
    (void)n_in;
    (void)out_size;
    const float* x = (const float*)d_in[0];    // [16,4096,256]
    const float* Wi = (const float*)d_in[1];   // [3,2,256,384]
    const float* Wh = (const float*)d_in[2];   // [3,2,128,384]
    const float* bh = (const float*)d_in[3];   // [3,2,384]
    float* out = (float*)d_out;                // [16,4096,256]

    init_sync<<<13, 256>>>();
    mega<<<148, 384>>>(x, Wi, Wh, bh, out);
}